// round 13
// baseline (speedup 1.0000x reference)
#include <cuda_runtime.h>
#include <math.h>

// Problem dims
#define L_ 16
#define H_ 8
#define D_ 768
#define DH_ 96
#define F_ 2048
#define V_ 32000
#define B_ 2
#define S_ 1024
#define BS_ (B_ * S_)
#define EPS_ 1e-6f

// Activation scratch (padded so unpredicated tile loads stay in-bounds)
__device__ float g_x[BS_ * D_ + 256];
__device__ float g_xn[BS_ * D_ + 256];
__device__ float g_q[BS_ * D_ + 256];
__device__ float g_k[BS_ * D_ + 256];
__device__ float g_v[BS_ * D_ + 256];
__device__ float g_o[BS_ * D_ + 256];
__device__ float g_ffn[BS_ * F_ + 256];

// TF32-rounded weight copies
__device__ float g_cwq[L_ * D_ * D_];
__device__ float g_cwk[L_ * D_ * D_];
__device__ float g_cwv[L_ * D_ * D_];
__device__ float g_cwo[L_ * D_ * D_];
__device__ float g_cw1[(long long)L_ * D_ * F_];
__device__ float g_cw2[(long long)L_ * F_ * D_];
__device__ float g_cow[(long long)D_ * V_];

struct MultiPtr {
    const float* B[3];
    float* C[3];
};

__device__ __forceinline__ unsigned f2tf32(float x) {
    unsigned r;
    asm("cvt.rna.tf32.f32 %0, %1;" : "=r"(r) : "f"(x));
    return r;
}
__device__ __forceinline__ float roundtf(float x) { return __uint_as_float(f2tf32(x)); }

// ---------------------------------------------------------------------------
// Weight -> TF32 rounding (4x unrolled grid-stride)
// ---------------------------------------------------------------------------
__device__ __forceinline__ float4 rtf4(float4 v) {
    v.x = roundtf(v.x); v.y = roundtf(v.y); v.z = roundtf(v.z); v.w = roundtf(v.w);
    return v;
}

__global__ void cvt_tf32_kernel(const float4* __restrict__ in, float4* __restrict__ out,
                                long long n4) {
    long long stride = (long long)gridDim.x * blockDim.x;
    long long i = (long long)blockIdx.x * blockDim.x + threadIdx.x;
    for (; i + 3 * stride < n4; i += 4 * stride) {
        float4 a = in[i];
        float4 b = in[i + stride];
        float4 c = in[i + 2 * stride];
        float4 d = in[i + 3 * stride];
        out[i]              = rtf4(a);
        out[i + stride]     = rtf4(b);
        out[i + 2 * stride] = rtf4(c);
        out[i + 3 * stride] = rtf4(d);
    }
    for (; i < n4; i += stride) out[i] = rtf4(in[i]);
}

// ---------------------------------------------------------------------------
// Fused embedding + RMSNorm
// ---------------------------------------------------------------------------
__global__ void embed_norm_kernel(const int* __restrict__ tok,
                                  const float* __restrict__ tok_emb,
                                  const float* __restrict__ pos_emb,
                                  const float* __restrict__ w) {
    int row = blockIdx.x;
    int s = row % S_;
    int t = tok[row];
    __shared__ float buf[D_];
    __shared__ float red[256];
    float ss = 0.f;
    for (int d = threadIdx.x; d < D_; d += 256) {
        float v = tok_emb[(long long)t * D_ + d] + pos_emb[(long long)s * D_ + d];
        buf[d] = v;
        ss += v * v;
    }
    red[threadIdx.x] = ss;
    __syncthreads();
    for (int o = 128; o > 0; o >>= 1) {
        if (threadIdx.x < o) red[threadIdx.x] += red[threadIdx.x + o];
        __syncthreads();
    }
    float inv = rsqrtf(red[0] / (float)D_ + EPS_);
    for (int d = threadIdx.x; d < D_; d += 256)
        g_x[(long long)row * D_ + d] = buf[d] * inv * w[d];
}

// ---------------------------------------------------------------------------
// RMSNorm (row = 768 = 192 threads x float4); output rounded to tf32
// ---------------------------------------------------------------------------
__global__ void __launch_bounds__(192) rmsnorm_kernel(const float* __restrict__ in,
                                                      float* __restrict__ out,
                                                      const float* __restrict__ w) {
    long long row = blockIdx.x;
    int tid = threadIdx.x;
    const float4* x4 = (const float4*)(in + row * D_);
    float4 v = x4[tid];
    float ss = v.x * v.x + v.y * v.y + v.z * v.z + v.w * v.w;
    #pragma unroll
    for (int o = 16; o > 0; o >>= 1) ss += __shfl_xor_sync(~0u, ss, o);
    __shared__ float red[6];
    if ((tid & 31) == 0) red[tid >> 5] = ss;
    __syncthreads();
    float tot = red[0] + red[1] + red[2] + red[3] + red[4] + red[5];
    float inv = rsqrtf(tot * (1.f / (float)D_) + EPS_);
    float4 wv = ((const float4*)w)[tid];
    float4 y;
    y.x = roundtf(v.x * inv * wv.x);
    y.y = roundtf(v.y * inv * wv.y);
    y.z = roundtf(v.z * inv * wv.z);
    y.w = roundtf(v.w * inv * wv.w);
    ((float4*)(out + row * D_))[tid] = y;
}

// ---------------------------------------------------------------------------
// Shared MMA helpers
// ---------------------------------------------------------------------------
__device__ __forceinline__ void cp16(float* dst, const float* src) {
    unsigned d = (unsigned)__cvta_generic_to_shared(dst);
    asm volatile("cp.async.cg.shared.global [%0], [%1], 16;" :: "r"(d), "l"(src));
}

__device__ __forceinline__ void mma_tf32(float* d, const unsigned* a, const unsigned* b) {
    asm volatile("mma.sync.aligned.m16n8k8.row.col.f32.tf32.tf32.f32 "
                 "{%0,%1,%2,%3}, {%4,%5,%6,%7}, {%8,%9}, {%0,%1,%2,%3};"
                 : "+f"(d[0]), "+f"(d[1]), "+f"(d[2]), "+f"(d[3])
                 : "r"(a[0]), "r"(a[1]), "r"(a[2]), "r"(a[3]),
                   "r"(b[0]), "r"(b[1]));
}

__device__ __forceinline__ float gelu_tanh(float x) {
    return 0.5f * x * (1.f + tanhf(0.7978845608028654f * (x + 0.044715f * x * x * x)));
}

// ---------------------------------------------------------------------------
// Fused causal flash attention (unchanged — known good)
// ---------------------------------------------------------------------------
#define QSTR 100
#define VSTR 104
#define PSTR 68
#define KBUF (64 * QSTR)
#define VBUF (64 * VSTR)
#define OFF_K (128 * QSTR)
#define OFF_V (OFF_K + 2 * KBUF)
#define OFF_P (OFF_V + 2 * VBUF)
#define ATT_SMEM ((OFF_P + 128 * PSTR) * 4)

__global__ void __launch_bounds__(256) attn_fused_kernel(
    const float* __restrict__ q, const float* __restrict__ k,
    const float* __restrict__ v, float* __restrict__ o, float scale)
{
    int mb = blockIdx.x;
    int z = blockIdx.y;
    int b = z >> 3, h = z & 7;
    int m0 = mb * 128;
    long long qbase = ((long long)b * S_ + m0) * D_ + h * DH_;
    long long kvbase = ((long long)b * S_) * D_ + h * DH_;

    extern __shared__ float sm[];
    float* QS = sm;
    float* KS = sm + OFF_K;
    float* VS = sm + OFF_V;
    float* PS = sm + OFF_P;

    int tid = threadIdx.x;
    int warp = tid >> 5, lane = tid & 31;
    int g = lane >> 2, t = lane & 3;
    int wrow = warp * 16;

    #pragma unroll
    for (int i = 0; i < 12; i++) {
        int f = tid + i * 256;
        int r = f / 24, c = f % 24;
        cp16(QS + r * QSTR + c * 4, q + qbase + (long long)r * D_ + c * 4);
    }
    {
        #pragma unroll
        for (int i = 0; i < 6; i++) {
            int f = tid + i * 256;
            int r = f / 24, c = f % 24;
            cp16(KS + r * QSTR + c * 4, k + kvbase + (long long)r * D_ + c * 4);
        }
        #pragma unroll
        for (int i = 0; i < 6; i++) {
            int f = tid + i * 256;
            int r = f / 24, c = f % 24;
            cp16(VS + r * VSTR + c * 4, v + kvbase + (long long)r * D_ + c * 4);
        }
    }
    asm volatile("cp.async.commit_group;" ::: "memory");

    float accO[12][4];
    #pragma unroll
    for (int i = 0; i < 12; i++)
        #pragma unroll
        for (int r = 0; r < 4; r++) accO[i][r] = 0.f;
    float mrow[2] = {-1e30f, -1e30f};
    float lrow[2] = {0.f, 0.f};

    int kb_last = 2 * mb + 1;
    for (int kb = 0; kb <= kb_last; kb++) {
        asm volatile("cp.async.wait_group 0;" ::: "memory");
        __syncthreads();

        if (kb < kb_last) {
            int nb = (kb + 1) & 1;
            long long kr = kvbase + (long long)(kb + 1) * 64 * D_;
            #pragma unroll
            for (int i = 0; i < 6; i++) {
                int f = tid + i * 256;
                int r = f / 24, c = f % 24;
                cp16(KS + nb * KBUF + r * QSTR + c * 4, k + kr + (long long)r * D_ + c * 4);
            }
            #pragma unroll
            for (int i = 0; i < 6; i++) {
                int f = tid + i * 256;
                int r = f / 24, c = f % 24;
                cp16(VS + nb * VBUF + r * VSTR + c * 4, v + kr + (long long)r * D_ + c * 4);
            }
            asm volatile("cp.async.commit_group;" ::: "memory");
        }

        const unsigned* Qu = (const unsigned*)QS;
        const unsigned* Ku = (const unsigned*)(KS + (kb & 1) * KBUF);
        const unsigned* Vu = (const unsigned*)(VS + (kb & 1) * VBUF);

        float s[8][4];
        #pragma unroll
        for (int i = 0; i < 8; i++)
            #pragma unroll
            for (int r = 0; r < 4; r++) s[i][r] = 0.f;

        #pragma unroll
        for (int ks = 0; ks < 12; ks++) {
            int krow = ks * 8 + t;
            unsigned af[4];
            af[0] = Qu[(wrow + g) * QSTR + krow];
            af[1] = Qu[(wrow + g + 8) * QSTR + krow];
            af[2] = Qu[(wrow + g) * QSTR + krow + 4];
            af[3] = Qu[(wrow + g + 8) * QSTR + krow + 4];
            #pragma unroll
            for (int nt = 0; nt < 8; nt++) {
                int n = nt * 8 + g;
                unsigned bf[2];
                bf[0] = Ku[n * QSTR + krow];
                bf[1] = Ku[n * QSTR + krow + 4];
                mma_tf32(s[nt], af, bf);
            }
        }

        int j0 = kb * 64;
        #pragma unroll
        for (int nt = 0; nt < 8; nt++) {
            #pragma unroll
            for (int r = 0; r < 4; r++) {
                int row = m0 + wrow + g + ((r & 2) ? 8 : 0);
                int col = j0 + nt * 8 + 2 * t + (r & 1);
                float val = s[nt][r] * scale;
                s[nt][r] = (col > row) ? -1e30f : val;
            }
        }

        #pragma unroll
        for (int hh = 0; hh < 2; hh++) {
            float mx = -1e30f;
            #pragma unroll
            for (int nt = 0; nt < 8; nt++)
                mx = fmaxf(mx, fmaxf(s[nt][2 * hh], s[nt][2 * hh + 1]));
            mx = fmaxf(mx, __shfl_xor_sync(~0u, mx, 1));
            mx = fmaxf(mx, __shfl_xor_sync(~0u, mx, 2));
            float mnew = fmaxf(mrow[hh], mx);
            float alpha = __expf(mrow[hh] - mnew);
            mrow[hh] = mnew;
            #pragma unroll
            for (int nt = 0; nt < 12; nt++) {
                accO[nt][2 * hh]     *= alpha;
                accO[nt][2 * hh + 1] *= alpha;
            }
            float sum = 0.f;
            #pragma unroll
            for (int nt = 0; nt < 8; nt++) {
                float p0 = __expf(s[nt][2 * hh] - mnew);
                float p1 = __expf(s[nt][2 * hh + 1] - mnew);
                s[nt][2 * hh] = p0;
                s[nt][2 * hh + 1] = p1;
                sum += p0 + p1;
            }
            sum += __shfl_xor_sync(~0u, sum, 1);
            sum += __shfl_xor_sync(~0u, sum, 2);
            lrow[hh] = lrow[hh] * alpha + sum;
        }

        #pragma unroll
        for (int nt = 0; nt < 8; nt++) {
            #pragma unroll
            for (int r = 0; r < 4; r++) {
                int row = wrow + g + ((r & 2) ? 8 : 0);
                int col = nt * 8 + 2 * t + (r & 1);
                PS[row * PSTR + col] = roundtf(s[nt][r]);
            }
        }

        const unsigned* Pu = (const unsigned*)PS;
        #pragma unroll
        for (int ks = 0; ks < 8; ks++) {
            int krow = ks * 8 + t;
            unsigned af[4];
            af[0] = Pu[(wrow + g) * PSTR + krow];
            af[1] = Pu[(wrow + g + 8) * PSTR + krow];
            af[2] = Pu[(wrow + g) * PSTR + krow + 4];
            af[3] = Pu[(wrow + g + 8) * PSTR + krow + 4];
            #pragma unroll
            for (int nt = 0; nt < 12; nt++) {
                int n = nt * 8 + g;
                unsigned bf[2];
                bf[0] = Vu[krow * VSTR + n];
                bf[1] = Vu[(krow + 4) * VSTR + n];
                mma_tf32(accO[nt], af, bf);
            }
        }
    }

    float inv0 = 1.f / lrow[0];
    float inv1 = 1.f / lrow[1];
    #pragma unroll
    for (int nt = 0; nt < 12; nt++) {
        #pragma unroll
        for (int r = 0; r < 4; r++) {
            int row = wrow + g + ((r & 2) ? 8 : 0);
            int col = nt * 8 + 2 * t + (r & 1);
            float val = accO[nt][r] * ((r & 2) ? inv1 : inv0);
            o[qbase + (long long)row * D_ + col] = roundtf(val);
        }
    }
}

// ---------------------------------------------------------------------------
// BIG-tile GEMM: 256x128x32 block, 1 CTA/SM, warp tile 64x64 (acc = 128 regs).
// 32 MMAs per 32 LDS per k-slice (1.5x arithmetic intensity of small tile).
// Used for QKV / FFN1 / logits (grids >= 128 CTAs).
// ---------------------------------------------------------------------------
#define BIG_STAGE (256 * 36 + 32 * 136)   // 13568 floats
#define BIG_SMEM (3 * BIG_STAGE * 4)      // 162816 bytes

__global__ void __launch_bounds__(256, 1) gemm_big(
    const float* __restrict__ A, int lda,
    const float* __restrict__ Bp, int ldb,
    float* __restrict__ C, int ldc,
    int M, int N, int K, int gelu_flag, int round_flag, int mode,
    MultiPtr P, int nmulti)
{
    constexpr int BM = 256, BN = 128, BSTR = 136;
    extern __shared__ float smf[];

    int z = blockIdx.z;
    if (nmulti > 1) { Bp = P.B[z]; C = P.C[z]; }

    int m0, n0;
    if (mode == 1) { m0 = blockIdx.x * BM; n0 = blockIdx.y * BN; }
    else           { m0 = blockIdx.y * BM; n0 = blockIdx.x * BN; }

    int tid = threadIdx.x;
    int warp = tid >> 5, lane = tid & 31;
    int g = lane >> 2, t = lane & 3;
    int mwarp = (warp & 3) * 64;
    int nwarp = (warp >> 2) * 64;

    float acc[4][8][4];
    #pragma unroll
    for (int i = 0; i < 4; i++)
        #pragma unroll
        for (int j = 0; j < 8; j++)
            #pragma unroll
            for (int r = 0; r < 4; r++) acc[i][j][r] = 0.f;

    const int KT = K >> 5;

    auto stage = [&](int kt, int sbuf) {
        float* Asf = smf + sbuf * BIG_STAGE;
        float* Bsf = Asf + BM * 36;
        int k0 = kt * 32;
        #pragma unroll
        for (int i = 0; i < 8; i++) {
            int f = tid + i * 256;
            int row = f >> 3, ch = f & 7;
            cp16(Asf + row * 36 + ch * 4,
                 A + (long long)(m0 + row) * lda + k0 + ch * 4);
        }
        #pragma unroll
        for (int i = 0; i < 4; i++) {
            int f = tid + i * 256;
            int kk = f >> 5, ch = f & 31;
            cp16(Bsf + kk * BSTR + ch * 4,
                 Bp + (long long)(k0 + kk) * ldb + n0 + ch * 4);
        }
        asm volatile("cp.async.commit_group;" ::: "memory");
    };

    for (int s = 0; s < 2 && s < KT; s++) stage(s, s);

    for (int kt = 0; kt < KT; kt++) {
        if (kt == KT - 1) asm volatile("cp.async.wait_group 0;" ::: "memory");
        else              asm volatile("cp.async.wait_group 1;" ::: "memory");
        __syncthreads();

        int nk = kt + 2;
        if (nk < KT) stage(nk, nk % 3);

        const unsigned* Asu = (const unsigned*)(smf + (kt % 3) * BIG_STAGE);
        const unsigned* Bsu = Asu + BM * 36;

        #pragma unroll
        for (int ks = 0; ks < 4; ks++) {
            int krow = ks * 8 + t;
            unsigned af[4][4];
            #pragma unroll
            for (int mt = 0; mt < 4; mt++) {
                int m = mwarp + mt * 16 + g;
                af[mt][0] = Asu[m * 36 + krow];
                af[mt][1] = Asu[(m + 8) * 36 + krow];
                af[mt][2] = Asu[m * 36 + krow + 4];
                af[mt][3] = Asu[(m + 8) * 36 + krow + 4];
            }
            unsigned bf[8][2];
            #pragma unroll
            for (int nt = 0; nt < 8; nt++) {
                int n = nwarp + nt * 8 + g;
                bf[nt][0] = Bsu[krow * BSTR + n];
                bf[nt][1] = Bsu[(krow + 4) * BSTR + n];
            }
            #pragma unroll
            for (int mt = 0; mt < 4; mt++)
                #pragma unroll
                for (int nt = 0; nt < 8; nt++)
                    mma_tf32(acc[mt][nt], af[mt], bf[nt]);
        }
    }

    #pragma unroll
    for (int mt = 0; mt < 4; mt++) {
        #pragma unroll
        for (int nt = 0; nt < 8; nt++) {
            #pragma unroll
            for (int r = 0; r < 4; r++) {
                int row = m0 + mwarp + mt * 16 + g + ((r & 2) ? 8 : 0);
                int col = n0 + nwarp + nt * 8 + t * 2 + (r & 1);
                if (row < M && col < N) {
                    float v = acc[mt][nt][r];
                    if (gelu_flag) v = gelu_tanh(v);
                    if (round_flag) v = roundtf(v);
                    C[(long long)row * ldc + col] = v;
                }
            }
        }
    }
}

// ---------------------------------------------------------------------------
// Small-tile GEMM (2 CTA/SM), for O-proj / FFN2 (small grids)
// ---------------------------------------------------------------------------
template <bool TRANSB, int BM, int BN, int PP>
__global__ void __launch_bounds__(256, 2) gemm_tc_async(
    const float* __restrict__ A, int lda, long long saO, long long saI,
    const float* __restrict__ Bp, int ldb, long long sbO, long long sbI,
    float* __restrict__ C, int ldc, long long scO, long long scI,
    const float* __restrict__ R,
    int M, int N, int K, float alpha, int gelu_flag, int round_flag,
    int mode, int kcap, int hdiv, MultiPtr P, int nmulti)
{
    constexpr int WM = BM / 32;
    constexpr int WN = 8 / WM;
    constexpr int WTN = BN / WN;
    constexpr int NT = WTN / 8;
    constexpr int BSTR = BN + 8;
    constexpr int BFLc = TRANSB ? BN * 36 : 32 * BSTR;
    constexpr int STAGE = BM * 36 + BFLc;
    constexpr int BCH = BN / 4;

    extern __shared__ float smf[];

    int z = blockIdx.z;
    if (nmulti > 1) {
        Bp = P.B[z];
        C = P.C[z];
    } else {
        int zo = z / hdiv, zi = z % hdiv;
        A  += (long long)zo * saO + (long long)zi * saI;
        Bp += (long long)zo * sbO + (long long)zi * sbI;
        long long co = (long long)zo * scO + (long long)zi * scI;
        C += co;
        if (R) R += co;
    }

    int m0, n0;
    if (mode == 2) {
        int p = blockIdx.x;
        int bm = 0;
        while ((bm + 1) * (bm + 2) / 2 <= p) bm++;
        int bn = p - bm * (bm + 1) / 2;
        m0 = bm * BM; n0 = bn * BN;
    } else if (mode == 1) {
        m0 = blockIdx.x * BM; n0 = blockIdx.y * BN;
    } else {
        m0 = blockIdx.y * BM; n0 = blockIdx.x * BN;
    }
    if (kcap) K = min(K, m0 + BM);

    int tid = threadIdx.x;
    int warp = tid >> 5, lane = tid & 31;
    int g = lane >> 2, t = lane & 3;
    int mwarp = (warp % WM) * 32;
    int nwarp = (warp / WM) * WTN;

    float acc[2][NT][4];
    #pragma unroll
    for (int i = 0; i < 2; i++)
        #pragma unroll
        for (int j = 0; j < NT; j++)
            #pragma unroll
            for (int r = 0; r < 4; r++) acc[i][j][r] = 0.f;

    const int KT = K >> 5;

    auto stage = [&](int kt, int sbuf) {
        float* Asf = smf + sbuf * STAGE;
        float* Bsf = Asf + BM * 36;
        int k0 = kt * 32;
        #pragma unroll
        for (int i = 0; i < BM / 32; i++) {
            int f = tid + i * 256;
            int row = f >> 3, ch = f & 7;
            cp16(Asf + row * 36 + ch * 4,
                 A + (long long)(m0 + row) * lda + k0 + ch * 4);
        }
        if (TRANSB) {
            #pragma unroll
            for (int i = 0; i < BN / 32; i++) {
                int f = tid + i * 256;
                int row = f >> 3, ch = f & 7;
                cp16(Bsf + row * 36 + ch * 4,
                     Bp + (long long)(n0 + row) * ldb + k0 + ch * 4);
            }
        } else {
            #pragma unroll
            for (int i = 0; i < (32 * BCH) / 256; i++) {
                int f = tid + i * 256;
                int kk = f / BCH, ch = f % BCH;
                cp16(Bsf + kk * BSTR + ch * 4,
                     Bp + (long long)(k0 + kk) * ldb + n0 + ch * 4);
            }
        }
        asm volatile("cp.async.commit_group;" ::: "memory");
    };

    for (int s = 0; s < PP - 1 && s < KT; s++) stage(s, s);

    for (int kt = 0; kt < KT; kt++) {
        if (kt == KT - 1) asm volatile("cp.async.wait_group 0;" ::: "memory");
        else              asm volatile("cp.async.wait_group %0;" :: "n"(PP - 2) : "memory");
        __syncthreads();

        int nk = kt + PP - 1;
        if (nk < KT) stage(nk, nk % PP);

        const unsigned* Asu = (const unsigned*)(smf + (kt % PP) * STAGE);
        const unsigned* Bsu = Asu + BM * 36;

        #pragma unroll
        for (int ks = 0; ks < 4; ks++) {
            int krow = ks * 8 + t;
            unsigned af[2][4];
            #pragma unroll
            for (int mt = 0; mt < 2; mt++) {
                int m = mwarp + mt * 16 + g;
                af[mt][0] = Asu[m * 36 + krow];
                af[mt][1] = Asu[(m + 8) * 36 + krow];
                af[mt][2] = Asu[m * 36 + krow + 4];
                af[mt][3] = Asu[(m + 8) * 36 + krow + 4];
            }
            unsigned bf[NT][2];
            #pragma unroll
            for (int nt = 0; nt < NT; nt++) {
                int n = nwarp + nt * 8 + g;
                if (TRANSB) {
                    bf[nt][0] = Bsu[n * 36 + krow];
                    bf[nt][1] = Bsu[n * 36 + krow + 4];
                } else {
                    bf[nt][0] = Bsu[krow * BSTR + n];
                    bf[nt][1] = Bsu[(krow + 4) * BSTR + n];
                }
            }
            #pragma unroll
            for (int mt = 0; mt < 2; mt++)
                #pragma unroll
                for (int nt = 0; nt < NT; nt++)
                    mma_tf32(acc[mt][nt], af[mt], bf[nt]);
        }
    }

    #pragma unroll
    for (int mt = 0; mt < 2; mt++) {
        #pragma unroll
        for (int nt = 0; nt < NT; nt++) {
            #pragma unroll
            for (int r = 0; r < 4; r++) {
                int row = m0 + mwarp + mt * 16 + g + ((r & 2) ? 8 : 0);
                int col = n0 + nwarp + nt * 8 + t * 2 + (r & 1);
                if (row < M && col < N) {
                    float v = acc[mt][nt][r] * alpha;
                    if (R) v += R[(long long)row * ldc + col];
                    if (gelu_flag) v = gelu_tanh(v);
                    if (round_flag) v = roundtf(v);
                    C[(long long)row * ldc + col] = v;
                }
            }
        }
    }
}

// ---------------------------------------------------------------------------
// Host launch helpers
// ---------------------------------------------------------------------------
template <bool TB, int BM, int BN, int PP>
static void run_gemm(dim3 grid,
                     const float* A, int lda, long long saO, long long saI,
                     const float* Bp, int ldb, long long sbO, long long sbI,
                     float* C, int ldc, long long scO, long long scI,
                     const float* R, int M, int N, int K,
                     float alpha, int gelu_flag, int round_flag,
                     int mode, int kcap, int hdiv, MultiPtr mp, int nmulti)
{
    constexpr int BFLc = TB ? BN * 36 : 32 * (BN + 8);
    size_t smem = (size_t)PP * (BM * 36 + BFLc) * sizeof(float);
    cudaFuncSetAttribute(gemm_tc_async<TB, BM, BN, PP>,
                         cudaFuncAttributeMaxDynamicSharedMemorySize, (int)smem);
    gemm_tc_async<TB, BM, BN, PP><<<grid, 256, smem>>>(A, lda, saO, saI, Bp, ldb, sbO, sbI,
                                                       C, ldc, scO, scI, R, M, N, K,
                                                       alpha, gelu_flag, round_flag,
                                                       mode, kcap, hdiv, mp, nmulti);
}

static void run_big(dim3 grid, const float* A, int lda, const float* Bp, int ldb,
                    float* C, int ldc, int M, int N, int K,
                    int gelu_flag, int round_flag, int mode, MultiPtr mp, int nmulti)
{
    gemm_big<<<grid, 256, BIG_SMEM>>>(A, lda, Bp, ldb, C, ldc, M, N, K,
                                      gelu_flag, round_flag, mode, mp, nmulti);
}

static void cvt_weights(const float* src, float* dst, long long n) {
    cvt_tf32_kernel<<<2368, 256>>>((const float4*)src, (float4*)dst, n >> 2);
}

extern "C" void kernel_launch(void* const* d_in, const int* in_sizes, int n_in,
                              void* d_out, int out_size) {
    const int*   tok         = (const int*)d_in[0];
    const float* tok_emb     = (const float*)d_in[1];
    const float* pos_emb     = (const float*)d_in[2];
    const float* pos_norm_w  = (const float*)d_in[3];
    const float* attn_norm_w = (const float*)d_in[4];
    const float* wq          = (const float*)d_in[5];
    const float* wk          = (const float*)d_in[6];
    const float* wv          = (const float*)d_in[7];
    const float* wo          = (const float*)d_in[8];
    const float* ffn_norm_w  = (const float*)d_in[9];
    const float* w1          = (const float*)d_in[10];
    const float* w2          = (const float*)d_in[11];
    const float* out_norm_w  = (const float*)d_in[12];
    const float* out_w       = (const float*)d_in[13];
    float* out = (float*)d_out;

    float *x, *xn, *q, *k, *v, *o, *ffn;
    float *cwq, *cwk, *cwv, *cwo, *cw1, *cw2, *cow;
    cudaGetSymbolAddress((void**)&x,   g_x);
    cudaGetSymbolAddress((void**)&xn,  g_xn);
    cudaGetSymbolAddress((void**)&q,   g_q);
    cudaGetSymbolAddress((void**)&k,   g_k);
    cudaGetSymbolAddress((void**)&v,   g_v);
    cudaGetSymbolAddress((void**)&o,   g_o);
    cudaGetSymbolAddress((void**)&ffn, g_ffn);
    cudaGetSymbolAddress((void**)&cwq, g_cwq);
    cudaGetSymbolAddress((void**)&cwk, g_cwk);
    cudaGetSymbolAddress((void**)&cwv, g_cwv);
    cudaGetSymbolAddress((void**)&cwo, g_cwo);
    cudaGetSymbolAddress((void**)&cw1, g_cw1);
    cudaGetSymbolAddress((void**)&cw2, g_cw2);
    cudaGetSymbolAddress((void**)&cow, g_cow);

    const float scale = 0.102062072615966f;  // 1/sqrt(96)
    MultiPtr mp0 = {};

    // Pre-round weights to tf32
    cvt_weights(wq, cwq, (long long)L_ * D_ * D_);
    cvt_weights(wk, cwk, (long long)L_ * D_ * D_);
    cvt_weights(wv, cwv, (long long)L_ * D_ * D_);
    cvt_weights(wo, cwo, (long long)L_ * D_ * D_);
    cvt_weights(w1, cw1, (long long)L_ * D_ * F_);
    cvt_weights(w2, cw2, (long long)L_ * F_ * D_);
    cvt_weights(out_w, cow, (long long)D_ * V_);

    cudaFuncSetAttribute(attn_fused_kernel,
                         cudaFuncAttributeMaxDynamicSharedMemorySize, ATT_SMEM);
    cudaFuncSetAttribute(gemm_big,
                         cudaFuncAttributeMaxDynamicSharedMemorySize, BIG_SMEM);

    embed_norm_kernel<<<BS_, 256>>>(tok, tok_emb, pos_emb, pos_norm_w);

    for (int l = 0; l < L_; l++) {
        const float* lwq = cwq + (long long)l * D_ * D_;
        const float* lwk = cwk + (long long)l * D_ * D_;
        const float* lwv = cwv + (long long)l * D_ * D_;
        const float* lwo = cwo + (long long)l * D_ * D_;
        const float* lw1 = cw1 + (long long)l * D_ * F_;
        const float* lw2 = cw2 + (long long)l * F_ * D_;

        rmsnorm_kernel<<<BS_, 192>>>(x, xn, attn_norm_w + (long long)l * D_);

        // fused QKV on big-tile kernel (144 CTAs)
        MultiPtr mq;
        mq.B[0] = lwq; mq.B[1] = lwk; mq.B[2] = lwv;
        mq.C[0] = q;   mq.C[1] = k;   mq.C[2] = v;
        run_big(dim3(6, 8, 3), xn, D_, lwq, D_, q, D_,
                BS_, D_, D_, 0, 1, 0, mq, 3);

        // fused causal attention
        attn_fused_kernel<<<dim3(8, 16), 256, ATT_SMEM>>>(q, k, v, o, scale);

        // x = x + o @ wo (small-tile, PIPE=4)
        run_gemm<false, 64, 128, 4>(dim3(6, 32, 1),
                                    o, D_, 0, 0, lwo, D_, 0, 0, x, D_, 0, 0,
                                    x, BS_, D_, D_, 1.f, 0, 0, 0, 0, 1, mp0, 1);

        rmsnorm_kernel<<<BS_, 192>>>(x, xn, ffn_norm_w + (long long)l * D_);

        // ffn = round(gelu(xn @ w1)) on big-tile kernel (128 CTAs)
        run_big(dim3(16, 8, 1), xn, D_, lw1, F_, ffn, F_,
                BS_, F_, D_, 1, 1, 0, mp0, 1);

        // x = x + ffn @ w2 (small-tile, PIPE=4)
        run_gemm<false, 64, 128, 4>(dim3(6, 32, 1),
                                    ffn, F_, 0, 0, lw2, D_, 0, 0, x, D_, 0, 0,
                                    x, BS_, D_, F_, 1.f, 0, 0, 0, 0, 1, mp0, 1);
    }

    rmsnorm_kernel<<<BS_, 192>>>(x, xn, out_norm_w);
    // logits on big-tile kernel, swapped raster (m fastest) for out_w L2 reuse
    run_big(dim3(8, 250, 1), xn, D_, cow, V_, out, V_,
            BS_, V_, D_, 0, 0, 1, mp0, 1);
}

// round 14
// speedup vs baseline: 1.0299x; 1.0299x over previous
#include <cuda_runtime.h>
#include <math.h>

// Problem dims
#define L_ 16
#define H_ 8
#define D_ 768
#define DH_ 96
#define F_ 2048
#define V_ 32000
#define B_ 2
#define S_ 1024
#define BS_ (B_ * S_)
#define EPS_ 1e-6f

// Activation scratch (padded so unpredicated tile loads stay in-bounds)
__device__ float g_x[BS_ * D_ + 256];
__device__ float g_xn[BS_ * D_ + 256];
__device__ float g_q[BS_ * D_ + 256];
__device__ float g_k[BS_ * D_ + 256];
__device__ float g_v[BS_ * D_ + 256];
__device__ float g_o[BS_ * D_ + 256];
__device__ float g_ffn[BS_ * F_ + 256];

// TF32-rounded weight copies
__device__ float g_cwq[L_ * D_ * D_];
__device__ float g_cwk[L_ * D_ * D_];
__device__ float g_cwv[L_ * D_ * D_];
__device__ float g_cwo[L_ * D_ * D_];
__device__ float g_cw1[(long long)L_ * D_ * F_];
__device__ float g_cw2[(long long)L_ * F_ * D_];
__device__ float g_cow[(long long)D_ * V_];

struct MultiPtr {
    const float* B[3];
    float* C[3];
};

__device__ __forceinline__ unsigned f2tf32(float x) {
    unsigned r;
    asm("cvt.rna.tf32.f32 %0, %1;" : "=r"(r) : "f"(x));
    return r;
}
__device__ __forceinline__ float roundtf(float x) { return __uint_as_float(f2tf32(x)); }

// ---------------------------------------------------------------------------
// Weight -> TF32 rounding (4x unrolled grid-stride)
// ---------------------------------------------------------------------------
__device__ __forceinline__ float4 rtf4(float4 v) {
    v.x = roundtf(v.x); v.y = roundtf(v.y); v.z = roundtf(v.z); v.w = roundtf(v.w);
    return v;
}

__global__ void cvt_tf32_kernel(const float4* __restrict__ in, float4* __restrict__ out,
                                long long n4) {
    long long stride = (long long)gridDim.x * blockDim.x;
    long long i = (long long)blockIdx.x * blockDim.x + threadIdx.x;
    for (; i + 3 * stride < n4; i += 4 * stride) {
        float4 a = in[i];
        float4 b = in[i + stride];
        float4 c = in[i + 2 * stride];
        float4 d = in[i + 3 * stride];
        out[i]              = rtf4(a);
        out[i + stride]     = rtf4(b);
        out[i + 2 * stride] = rtf4(c);
        out[i + 3 * stride] = rtf4(d);
    }
    for (; i < n4; i += stride) out[i] = rtf4(in[i]);
}

// ---------------------------------------------------------------------------
// Fused embedding + RMSNorm
// ---------------------------------------------------------------------------
__global__ void embed_norm_kernel(const int* __restrict__ tok,
                                  const float* __restrict__ tok_emb,
                                  const float* __restrict__ pos_emb,
                                  const float* __restrict__ w) {
    int row = blockIdx.x;
    int s = row % S_;
    int t = tok[row];
    __shared__ float buf[D_];
    __shared__ float red[256];
    float ss = 0.f;
    for (int d = threadIdx.x; d < D_; d += 256) {
        float v = tok_emb[(long long)t * D_ + d] + pos_emb[(long long)s * D_ + d];
        buf[d] = v;
        ss += v * v;
    }
    red[threadIdx.x] = ss;
    __syncthreads();
    for (int o = 128; o > 0; o >>= 1) {
        if (threadIdx.x < o) red[threadIdx.x] += red[threadIdx.x + o];
        __syncthreads();
    }
    float inv = rsqrtf(red[0] / (float)D_ + EPS_);
    for (int d = threadIdx.x; d < D_; d += 256)
        g_x[(long long)row * D_ + d] = buf[d] * inv * w[d];
}

// ---------------------------------------------------------------------------
// RMSNorm (row = 768 = 192 threads x float4); output rounded to tf32
// ---------------------------------------------------------------------------
__global__ void __launch_bounds__(192) rmsnorm_kernel(const float* __restrict__ in,
                                                      float* __restrict__ out,
                                                      const float* __restrict__ w) {
    long long row = blockIdx.x;
    int tid = threadIdx.x;
    const float4* x4 = (const float4*)(in + row * D_);
    float4 v = x4[tid];
    float ss = v.x * v.x + v.y * v.y + v.z * v.z + v.w * v.w;
    #pragma unroll
    for (int o = 16; o > 0; o >>= 1) ss += __shfl_xor_sync(~0u, ss, o);
    __shared__ float red[6];
    if ((tid & 31) == 0) red[tid >> 5] = ss;
    __syncthreads();
    float tot = red[0] + red[1] + red[2] + red[3] + red[4] + red[5];
    float inv = rsqrtf(tot * (1.f / (float)D_) + EPS_);
    float4 wv = ((const float4*)w)[tid];
    float4 y;
    y.x = roundtf(v.x * inv * wv.x);
    y.y = roundtf(v.y * inv * wv.y);
    y.z = roundtf(v.z * inv * wv.z);
    y.w = roundtf(v.w * inv * wv.w);
    ((float4*)(out + row * D_))[tid] = y;
}

// ---------------------------------------------------------------------------
// Shared MMA helpers
// ---------------------------------------------------------------------------
__device__ __forceinline__ void cp16(float* dst, const float* src) {
    unsigned d = (unsigned)__cvta_generic_to_shared(dst);
    asm volatile("cp.async.cg.shared.global [%0], [%1], 16;" :: "r"(d), "l"(src));
}

__device__ __forceinline__ void mma_tf32(float* d, const unsigned* a, const unsigned* b) {
    asm volatile("mma.sync.aligned.m16n8k8.row.col.f32.tf32.tf32.f32 "
                 "{%0,%1,%2,%3}, {%4,%5,%6,%7}, {%8,%9}, {%0,%1,%2,%3};"
                 : "+f"(d[0]), "+f"(d[1]), "+f"(d[2]), "+f"(d[3])
                 : "r"(a[0]), "r"(a[1]), "r"(a[2]), "r"(a[3]),
                   "r"(b[0]), "r"(b[1]));
}

// GELU(tanh approx) with HW MUFU.TANH (sm_75+); approx err ~1e-5 rel.
__device__ __forceinline__ float gelu_tanh(float x) {
    float u = 0.7978845608028654f * (x + 0.044715f * x * x * x);
    float th;
    asm("tanh.approx.f32 %0, %1;" : "=f"(th) : "f"(u));
    return 0.5f * x * (1.f + th);
}

// ---------------------------------------------------------------------------
// Fused causal flash attention (known good)
// ---------------------------------------------------------------------------
#define QSTR 100
#define VSTR 104
#define PSTR 68
#define KBUF (64 * QSTR)
#define VBUF (64 * VSTR)
#define OFF_K (128 * QSTR)
#define OFF_V (OFF_K + 2 * KBUF)
#define OFF_P (OFF_V + 2 * VBUF)
#define ATT_SMEM ((OFF_P + 128 * PSTR) * 4)

__global__ void __launch_bounds__(256) attn_fused_kernel(
    const float* __restrict__ q, const float* __restrict__ k,
    const float* __restrict__ v, float* __restrict__ o, float scale)
{
    int mb = blockIdx.x;
    int z = blockIdx.y;
    int b = z >> 3, h = z & 7;
    int m0 = mb * 128;
    long long qbase = ((long long)b * S_ + m0) * D_ + h * DH_;
    long long kvbase = ((long long)b * S_) * D_ + h * DH_;

    extern __shared__ float sm[];
    float* QS = sm;
    float* KS = sm + OFF_K;
    float* VS = sm + OFF_V;
    float* PS = sm + OFF_P;

    int tid = threadIdx.x;
    int warp = tid >> 5, lane = tid & 31;
    int g = lane >> 2, t = lane & 3;
    int wrow = warp * 16;

    #pragma unroll
    for (int i = 0; i < 12; i++) {
        int f = tid + i * 256;
        int r = f / 24, c = f % 24;
        cp16(QS + r * QSTR + c * 4, q + qbase + (long long)r * D_ + c * 4);
    }
    {
        #pragma unroll
        for (int i = 0; i < 6; i++) {
            int f = tid + i * 256;
            int r = f / 24, c = f % 24;
            cp16(KS + r * QSTR + c * 4, k + kvbase + (long long)r * D_ + c * 4);
        }
        #pragma unroll
        for (int i = 0; i < 6; i++) {
            int f = tid + i * 256;
            int r = f / 24, c = f % 24;
            cp16(VS + r * VSTR + c * 4, v + kvbase + (long long)r * D_ + c * 4);
        }
    }
    asm volatile("cp.async.commit_group;" ::: "memory");

    float accO[12][4];
    #pragma unroll
    for (int i = 0; i < 12; i++)
        #pragma unroll
        for (int r = 0; r < 4; r++) accO[i][r] = 0.f;
    float mrow[2] = {-1e30f, -1e30f};
    float lrow[2] = {0.f, 0.f};

    int kb_last = 2 * mb + 1;
    for (int kb = 0; kb <= kb_last; kb++) {
        asm volatile("cp.async.wait_group 0;" ::: "memory");
        __syncthreads();

        if (kb < kb_last) {
            int nb = (kb + 1) & 1;
            long long kr = kvbase + (long long)(kb + 1) * 64 * D_;
            #pragma unroll
            for (int i = 0; i < 6; i++) {
                int f = tid + i * 256;
                int r = f / 24, c = f % 24;
                cp16(KS + nb * KBUF + r * QSTR + c * 4, k + kr + (long long)r * D_ + c * 4);
            }
            #pragma unroll
            for (int i = 0; i < 6; i++) {
                int f = tid + i * 256;
                int r = f / 24, c = f % 24;
                cp16(VS + nb * VBUF + r * VSTR + c * 4, v + kr + (long long)r * D_ + c * 4);
            }
            asm volatile("cp.async.commit_group;" ::: "memory");
        }

        const unsigned* Qu = (const unsigned*)QS;
        const unsigned* Ku = (const unsigned*)(KS + (kb & 1) * KBUF);
        const unsigned* Vu = (const unsigned*)(VS + (kb & 1) * VBUF);

        float s[8][4];
        #pragma unroll
        for (int i = 0; i < 8; i++)
            #pragma unroll
            for (int r = 0; r < 4; r++) s[i][r] = 0.f;

        #pragma unroll
        for (int ks = 0; ks < 12; ks++) {
            int krow = ks * 8 + t;
            unsigned af[4];
            af[0] = Qu[(wrow + g) * QSTR + krow];
            af[1] = Qu[(wrow + g + 8) * QSTR + krow];
            af[2] = Qu[(wrow + g) * QSTR + krow + 4];
            af[3] = Qu[(wrow + g + 8) * QSTR + krow + 4];
            #pragma unroll
            for (int nt = 0; nt < 8; nt++) {
                int n = nt * 8 + g;
                unsigned bf[2];
                bf[0] = Ku[n * QSTR + krow];
                bf[1] = Ku[n * QSTR + krow + 4];
                mma_tf32(s[nt], af, bf);
            }
        }

        int j0 = kb * 64;
        #pragma unroll
        for (int nt = 0; nt < 8; nt++) {
            #pragma unroll
            for (int r = 0; r < 4; r++) {
                int row = m0 + wrow + g + ((r & 2) ? 8 : 0);
                int col = j0 + nt * 8 + 2 * t + (r & 1);
                float val = s[nt][r] * scale;
                s[nt][r] = (col > row) ? -1e30f : val;
            }
        }

        #pragma unroll
        for (int hh = 0; hh < 2; hh++) {
            float mx = -1e30f;
            #pragma unroll
            for (int nt = 0; nt < 8; nt++)
                mx = fmaxf(mx, fmaxf(s[nt][2 * hh], s[nt][2 * hh + 1]));
            mx = fmaxf(mx, __shfl_xor_sync(~0u, mx, 1));
            mx = fmaxf(mx, __shfl_xor_sync(~0u, mx, 2));
            float mnew = fmaxf(mrow[hh], mx);
            float alpha = __expf(mrow[hh] - mnew);
            mrow[hh] = mnew;
            #pragma unroll
            for (int nt = 0; nt < 12; nt++) {
                accO[nt][2 * hh]     *= alpha;
                accO[nt][2 * hh + 1] *= alpha;
            }
            float sum = 0.f;
            #pragma unroll
            for (int nt = 0; nt < 8; nt++) {
                float p0 = __expf(s[nt][2 * hh] - mnew);
                float p1 = __expf(s[nt][2 * hh + 1] - mnew);
                s[nt][2 * hh] = p0;
                s[nt][2 * hh + 1] = p1;
                sum += p0 + p1;
            }
            sum += __shfl_xor_sync(~0u, sum, 1);
            sum += __shfl_xor_sync(~0u, sum, 2);
            lrow[hh] = lrow[hh] * alpha + sum;
        }

        #pragma unroll
        for (int nt = 0; nt < 8; nt++) {
            #pragma unroll
            for (int r = 0; r < 4; r++) {
                int row = wrow + g + ((r & 2) ? 8 : 0);
                int col = nt * 8 + 2 * t + (r & 1);
                PS[row * PSTR + col] = roundtf(s[nt][r]);
            }
        }

        const unsigned* Pu = (const unsigned*)PS;
        #pragma unroll
        for (int ks = 0; ks < 8; ks++) {
            int krow = ks * 8 + t;
            unsigned af[4];
            af[0] = Pu[(wrow + g) * PSTR + krow];
            af[1] = Pu[(wrow + g + 8) * PSTR + krow];
            af[2] = Pu[(wrow + g) * PSTR + krow + 4];
            af[3] = Pu[(wrow + g + 8) * PSTR + krow + 4];
            #pragma unroll
            for (int nt = 0; nt < 12; nt++) {
                int n = nt * 8 + g;
                unsigned bf[2];
                bf[0] = Vu[krow * VSTR + n];
                bf[1] = Vu[(krow + 4) * VSTR + n];
                mma_tf32(accO[nt], af, bf);
            }
        }
    }

    float inv0 = 1.f / lrow[0];
    float inv1 = 1.f / lrow[1];
    #pragma unroll
    for (int nt = 0; nt < 12; nt++) {
        #pragma unroll
        for (int r = 0; r < 4; r++) {
            int row = wrow + g + ((r & 2) ? 8 : 0);
            int col = nt * 8 + 2 * t + (r & 1);
            float val = accO[nt][r] * ((r & 2) ? inv1 : inv0);
            o[qbase + (long long)row * D_ + col] = roundtf(val);
        }
    }
}

// ---------------------------------------------------------------------------
// TF32 tensor-core GEMM, cp.async PP-stage pipeline (single fragment buffer).
// 2 CTA/SM small-tile config — empirically optimal (R7/R12 both directions).
// ---------------------------------------------------------------------------
template <bool TRANSB, int BM, int BN, int PP>
__global__ void __launch_bounds__(256, 2) gemm_tc_async(
    const float* __restrict__ A, int lda, long long saO, long long saI,
    const float* __restrict__ Bp, int ldb, long long sbO, long long sbI,
    float* __restrict__ C, int ldc, long long scO, long long scI,
    const float* __restrict__ R,
    int M, int N, int K, float alpha, int gelu_flag, int round_flag,
    int mode, int kcap, int hdiv, MultiPtr P, int nmulti)
{
    constexpr int WM = BM / 32;
    constexpr int WN = 8 / WM;
    constexpr int WTN = BN / WN;
    constexpr int NT = WTN / 8;
    constexpr int BSTR = BN + 8;
    constexpr int BFLc = TRANSB ? BN * 36 : 32 * BSTR;
    constexpr int STAGE = BM * 36 + BFLc;
    constexpr int BCH = BN / 4;

    extern __shared__ float smf[];

    int z = blockIdx.z;
    if (nmulti > 1) {
        Bp = P.B[z];
        C = P.C[z];
    } else {
        int zo = z / hdiv, zi = z % hdiv;
        A  += (long long)zo * saO + (long long)zi * saI;
        Bp += (long long)zo * sbO + (long long)zi * sbI;
        long long co = (long long)zo * scO + (long long)zi * scI;
        C += co;
        if (R) R += co;
    }

    int m0, n0;
    if (mode == 2) {
        int p = blockIdx.x;
        int bm = 0;
        while ((bm + 1) * (bm + 2) / 2 <= p) bm++;
        int bn = p - bm * (bm + 1) / 2;
        m0 = bm * BM; n0 = bn * BN;
    } else if (mode == 1) {
        m0 = blockIdx.x * BM; n0 = blockIdx.y * BN;
    } else {
        m0 = blockIdx.y * BM; n0 = blockIdx.x * BN;
    }
    if (kcap) K = min(K, m0 + BM);

    int tid = threadIdx.x;
    int warp = tid >> 5, lane = tid & 31;
    int g = lane >> 2, t = lane & 3;
    int mwarp = (warp % WM) * 32;
    int nwarp = (warp / WM) * WTN;

    float acc[2][NT][4];
    #pragma unroll
    for (int i = 0; i < 2; i++)
        #pragma unroll
        for (int j = 0; j < NT; j++)
            #pragma unroll
            for (int r = 0; r < 4; r++) acc[i][j][r] = 0.f;

    const int KT = K >> 5;

    auto stage = [&](int kt, int sbuf) {
        float* Asf = smf + sbuf * STAGE;
        float* Bsf = Asf + BM * 36;
        int k0 = kt * 32;
        #pragma unroll
        for (int i = 0; i < BM / 32; i++) {
            int f = tid + i * 256;
            int row = f >> 3, ch = f & 7;
            cp16(Asf + row * 36 + ch * 4,
                 A + (long long)(m0 + row) * lda + k0 + ch * 4);
        }
        if (TRANSB) {
            #pragma unroll
            for (int i = 0; i < BN / 32; i++) {
                int f = tid + i * 256;
                int row = f >> 3, ch = f & 7;
                cp16(Bsf + row * 36 + ch * 4,
                     Bp + (long long)(n0 + row) * ldb + k0 + ch * 4);
            }
        } else {
            #pragma unroll
            for (int i = 0; i < (32 * BCH) / 256; i++) {
                int f = tid + i * 256;
                int kk = f / BCH, ch = f % BCH;
                cp16(Bsf + kk * BSTR + ch * 4,
                     Bp + (long long)(k0 + kk) * ldb + n0 + ch * 4);
            }
        }
        asm volatile("cp.async.commit_group;" ::: "memory");
    };

    for (int s = 0; s < PP - 1 && s < KT; s++) stage(s, s);

    for (int kt = 0; kt < KT; kt++) {
        if (kt == KT - 1) asm volatile("cp.async.wait_group 0;" ::: "memory");
        else              asm volatile("cp.async.wait_group %0;" :: "n"(PP - 2) : "memory");
        __syncthreads();

        int nk = kt + PP - 1;
        if (nk < KT) stage(nk, nk % PP);

        const unsigned* Asu = (const unsigned*)(smf + (kt % PP) * STAGE);
        const unsigned* Bsu = Asu + BM * 36;

        #pragma unroll
        for (int ks = 0; ks < 4; ks++) {
            int krow = ks * 8 + t;
            unsigned af[2][4];
            #pragma unroll
            for (int mt = 0; mt < 2; mt++) {
                int m = mwarp + mt * 16 + g;
                af[mt][0] = Asu[m * 36 + krow];
                af[mt][1] = Asu[(m + 8) * 36 + krow];
                af[mt][2] = Asu[m * 36 + krow + 4];
                af[mt][3] = Asu[(m + 8) * 36 + krow + 4];
            }
            unsigned bf[NT][2];
            #pragma unroll
            for (int nt = 0; nt < NT; nt++) {
                int n = nwarp + nt * 8 + g;
                if (TRANSB) {
                    bf[nt][0] = Bsu[n * 36 + krow];
                    bf[nt][1] = Bsu[n * 36 + krow + 4];
                } else {
                    bf[nt][0] = Bsu[krow * BSTR + n];
                    bf[nt][1] = Bsu[(krow + 4) * BSTR + n];
                }
            }
            #pragma unroll
            for (int mt = 0; mt < 2; mt++)
                #pragma unroll
                for (int nt = 0; nt < NT; nt++)
                    mma_tf32(acc[mt][nt], af[mt], bf[nt]);
        }
    }

    #pragma unroll
    for (int mt = 0; mt < 2; mt++) {
        #pragma unroll
        for (int nt = 0; nt < NT; nt++) {
            #pragma unroll
            for (int r = 0; r < 4; r++) {
                int row = m0 + mwarp + mt * 16 + g + ((r & 2) ? 8 : 0);
                int col = n0 + nwarp + nt * 8 + t * 2 + (r & 1);
                if (row < M && col < N) {
                    float v = acc[mt][nt][r] * alpha;
                    if (R) v += R[(long long)row * ldc + col];
                    if (gelu_flag) v = gelu_tanh(v);
                    if (round_flag) v = roundtf(v);
                    C[(long long)row * ldc + col] = v;
                }
            }
        }
    }
}

// ---------------------------------------------------------------------------
// Host launch helpers
// ---------------------------------------------------------------------------
template <bool TB, int BM, int BN, int PP>
static void run_gemm(dim3 grid,
                     const float* A, int lda, long long saO, long long saI,
                     const float* Bp, int ldb, long long sbO, long long sbI,
                     float* C, int ldc, long long scO, long long scI,
                     const float* R, int M, int N, int K,
                     float alpha, int gelu_flag, int round_flag,
                     int mode, int kcap, int hdiv, MultiPtr mp, int nmulti)
{
    constexpr int BFLc = TB ? BN * 36 : 32 * (BN + 8);
    size_t smem = (size_t)PP * (BM * 36 + BFLc) * sizeof(float);
    cudaFuncSetAttribute(gemm_tc_async<TB, BM, BN, PP>,
                         cudaFuncAttributeMaxDynamicSharedMemorySize, (int)smem);
    gemm_tc_async<TB, BM, BN, PP><<<grid, 256, smem>>>(A, lda, saO, saI, Bp, ldb, sbO, sbI,
                                                       C, ldc, scO, scI, R, M, N, K,
                                                       alpha, gelu_flag, round_flag,
                                                       mode, kcap, hdiv, mp, nmulti);
}

static void cvt_weights(const float* src, float* dst, long long n) {
    cvt_tf32_kernel<<<4736, 256>>>((const float4*)src, (float4*)dst, n >> 2);
}

extern "C" void kernel_launch(void* const* d_in, const int* in_sizes, int n_in,
                              void* d_out, int out_size) {
    const int*   tok         = (const int*)d_in[0];
    const float* tok_emb     = (const float*)d_in[1];
    const float* pos_emb     = (const float*)d_in[2];
    const float* pos_norm_w  = (const float*)d_in[3];
    const float* attn_norm_w = (const float*)d_in[4];
    const float* wq          = (const float*)d_in[5];
    const float* wk          = (const float*)d_in[6];
    const float* wv          = (const float*)d_in[7];
    const float* wo          = (const float*)d_in[8];
    const float* ffn_norm_w  = (const float*)d_in[9];
    const float* w1          = (const float*)d_in[10];
    const float* w2          = (const float*)d_in[11];
    const float* out_norm_w  = (const float*)d_in[12];
    const float* out_w       = (const float*)d_in[13];
    float* out = (float*)d_out;

    float *x, *xn, *q, *k, *v, *o, *ffn;
    float *cwq, *cwk, *cwv, *cwo, *cw1, *cw2, *cow;
    cudaGetSymbolAddress((void**)&x,   g_x);
    cudaGetSymbolAddress((void**)&xn,  g_xn);
    cudaGetSymbolAddress((void**)&q,   g_q);
    cudaGetSymbolAddress((void**)&k,   g_k);
    cudaGetSymbolAddress((void**)&v,   g_v);
    cudaGetSymbolAddress((void**)&o,   g_o);
    cudaGetSymbolAddress((void**)&ffn, g_ffn);
    cudaGetSymbolAddress((void**)&cwq, g_cwq);
    cudaGetSymbolAddress((void**)&cwk, g_cwk);
    cudaGetSymbolAddress((void**)&cwv, g_cwv);
    cudaGetSymbolAddress((void**)&cwo, g_cwo);
    cudaGetSymbolAddress((void**)&cw1, g_cw1);
    cudaGetSymbolAddress((void**)&cw2, g_cw2);
    cudaGetSymbolAddress((void**)&cow, g_cow);

    const float scale = 0.102062072615966f;  // 1/sqrt(96)
    MultiPtr mp0 = {};

    // Pre-round weights to tf32
    cvt_weights(wq, cwq, (long long)L_ * D_ * D_);
    cvt_weights(wk, cwk, (long long)L_ * D_ * D_);
    cvt_weights(wv, cwv, (long long)L_ * D_ * D_);
    cvt_weights(wo, cwo, (long long)L_ * D_ * D_);
    cvt_weights(w1, cw1, (long long)L_ * D_ * F_);
    cvt_weights(w2, cw2, (long long)L_ * F_ * D_);
    cvt_weights(out_w, cow, (long long)D_ * V_);

    cudaFuncSetAttribute(attn_fused_kernel,
                         cudaFuncAttributeMaxDynamicSharedMemorySize, ATT_SMEM);

    embed_norm_kernel<<<BS_, 256>>>(tok, tok_emb, pos_emb, pos_norm_w);

    for (int l = 0; l < L_; l++) {
        const float* lwq = cwq + (long long)l * D_ * D_;
        const float* lwk = cwk + (long long)l * D_ * D_;
        const float* lwv = cwv + (long long)l * D_ * D_;
        const float* lwo = cwo + (long long)l * D_ * D_;
        const float* lw1 = cw1 + (long long)l * D_ * F_;
        const float* lw2 = cw2 + (long long)l * F_ * D_;

        rmsnorm_kernel<<<BS_, 192>>>(x, xn, attn_norm_w + (long long)l * D_);

        // fused QKV (outputs rounded)
        MultiPtr mq;
        mq.B[0] = lwq; mq.B[1] = lwk; mq.B[2] = lwv;
        mq.C[0] = q;   mq.C[1] = k;   mq.C[2] = v;
        run_gemm<false, 128, 128, 3>(dim3(6, 16, 3),
                                     xn, D_, 0, 0, lwq, D_, 0, 0, q, D_, 0, 0,
                                     nullptr, BS_, D_, D_, 1.f, 0, 1, 0, 0, 1, mq, 3);

        // fused causal attention: o = softmax(scale * q k^T) v
        attn_fused_kernel<<<dim3(8, 16), 256, ATT_SMEM>>>(q, k, v, o, scale);

        // x = x + o @ wo  (PIPE=4)
        run_gemm<false, 64, 128, 4>(dim3(6, 32, 1),
                                    o, D_, 0, 0, lwo, D_, 0, 0, x, D_, 0, 0,
                                    x, BS_, D_, D_, 1.f, 0, 0, 0, 0, 1, mp0, 1);

        rmsnorm_kernel<<<BS_, 192>>>(x, xn, ffn_norm_w + (long long)l * D_);

        // ffn = round(gelu(xn @ w1))
        run_gemm<false, 128, 128, 3>(dim3(16, 16, 1),
                                     xn, D_, 0, 0, lw1, F_, 0, 0, ffn, F_, 0, 0,
                                     nullptr, BS_, F_, D_, 1.f, 1, 1, 0, 0, 1, mp0, 1);

        // x = x + ffn @ w2  (PIPE=4)
        run_gemm<false, 64, 128, 4>(dim3(6, 32, 1),
                                    ffn, F_, 0, 0, lw2, D_, 0, 0, x, D_, 0, 0,
                                    x, BS_, D_, F_, 1.f, 0, 0, 0, 0, 1, mp0, 1);
    }

    rmsnorm_kernel<<<BS_, 192>>>(x, xn, out_norm_w);
    // logits: swapped raster (m fastest) so concurrent CTAs share out_w tiles in L2
    run_gemm<false, 128, 128, 3>(dim3(16, 250, 1),
                                 xn, D_, 0, 0, cow, V_, 0, 0, out, V_, 0, 0,
                                 nullptr, BS_, V_, D_, 1.f, 0, 0, 1, 0, 1, mp0, 1);
}

// round 17
// speedup vs baseline: 1.0751x; 1.0439x over previous
#include <cuda_runtime.h>
#include <math.h>

// Problem dims
#define L_ 16
#define H_ 8
#define D_ 768
#define DH_ 96
#define F_ 2048
#define V_ 32000
#define B_ 2
#define S_ 1024
#define BS_ (B_ * S_)
#define EPS_ 1e-6f

// Activation scratch (padded so unpredicated tile loads stay in-bounds)
__device__ float g_x[BS_ * D_ + 256];
__device__ float g_xn[BS_ * D_ + 256];
__device__ float g_q[BS_ * D_ + 256];
__device__ float g_k[BS_ * D_ + 256];
__device__ float g_v[BS_ * D_ + 256];
__device__ float g_o[BS_ * D_ + 256];
__device__ float g_ffn[BS_ * F_ + 256];

// TF32-rounded weight copies
__device__ float g_cwq[L_ * D_ * D_];
__device__ float g_cwk[L_ * D_ * D_];
__device__ float g_cwv[L_ * D_ * D_];
__device__ float g_cwo[L_ * D_ * D_];
__device__ float g_cw1[(long long)L_ * D_ * F_];
__device__ float g_cw2[(long long)L_ * F_ * D_];
__device__ float g_cow[(long long)D_ * V_];

struct MultiPtr {
    const float* B[3];
    float* C[3];
};

__device__ __forceinline__ unsigned f2tf32(float x) {
    unsigned r;
    asm("cvt.rna.tf32.f32 %0, %1;" : "=r"(r) : "f"(x));
    return r;
}
__device__ __forceinline__ float roundtf(float x) { return __uint_as_float(f2tf32(x)); }

// ---------------------------------------------------------------------------
// Weight -> TF32 rounding (4x unrolled grid-stride)
// ---------------------------------------------------------------------------
__device__ __forceinline__ float4 rtf4(float4 v) {
    v.x = roundtf(v.x); v.y = roundtf(v.y); v.z = roundtf(v.z); v.w = roundtf(v.w);
    return v;
}

__global__ void cvt_tf32_kernel(const float4* __restrict__ in, float4* __restrict__ out,
                                long long n4) {
    long long stride = (long long)gridDim.x * blockDim.x;
    long long i = (long long)blockIdx.x * blockDim.x + threadIdx.x;
    for (; i + 3 * stride < n4; i += 4 * stride) {
        float4 a = in[i];
        float4 b = in[i + stride];
        float4 c = in[i + 2 * stride];
        float4 d = in[i + 3 * stride];
        out[i]              = rtf4(a);
        out[i + stride]     = rtf4(b);
        out[i + 2 * stride] = rtf4(c);
        out[i + 3 * stride] = rtf4(d);
    }
    for (; i < n4; i += stride) out[i] = rtf4(in[i]);
}

// ---------------------------------------------------------------------------
// Fused embedding + RMSNorm
// ---------------------------------------------------------------------------
__global__ void embed_norm_kernel(const int* __restrict__ tok,
                                  const float* __restrict__ tok_emb,
                                  const float* __restrict__ pos_emb,
                                  const float* __restrict__ w) {
    int row = blockIdx.x;
    int s = row % S_;
    int t = tok[row];
    __shared__ float buf[D_];
    __shared__ float red[256];
    float ss = 0.f;
    for (int d = threadIdx.x; d < D_; d += 256) {
        float v = tok_emb[(long long)t * D_ + d] + pos_emb[(long long)s * D_ + d];
        buf[d] = v;
        ss += v * v;
    }
    red[threadIdx.x] = ss;
    __syncthreads();
    for (int o = 128; o > 0; o >>= 1) {
        if (threadIdx.x < o) red[threadIdx.x] += red[threadIdx.x + o];
        __syncthreads();
    }
    float inv = rsqrtf(red[0] / (float)D_ + EPS_);
    for (int d = threadIdx.x; d < D_; d += 256)
        g_x[(long long)row * D_ + d] = buf[d] * inv * w[d];
}

// ---------------------------------------------------------------------------
// RMSNorm (row = 768 = 192 threads x float4); output rounded to tf32
// ---------------------------------------------------------------------------
__global__ void __launch_bounds__(192) rmsnorm_kernel(const float* __restrict__ in,
                                                      float* __restrict__ out,
                                                      const float* __restrict__ w) {
    long long row = blockIdx.x;
    int tid = threadIdx.x;
    const float4* x4 = (const float4*)(in + row * D_);
    float4 v = x4[tid];
    float ss = v.x * v.x + v.y * v.y + v.z * v.z + v.w * v.w;
    #pragma unroll
    for (int o = 16; o > 0; o >>= 1) ss += __shfl_xor_sync(~0u, ss, o);
    __shared__ float red[6];
    if ((tid & 31) == 0) red[tid >> 5] = ss;
    __syncthreads();
    float tot = red[0] + red[1] + red[2] + red[3] + red[4] + red[5];
    float inv = rsqrtf(tot * (1.f / (float)D_) + EPS_);
    float4 wv = ((const float4*)w)[tid];
    float4 y;
    y.x = roundtf(v.x * inv * wv.x);
    y.y = roundtf(v.y * inv * wv.y);
    y.z = roundtf(v.z * inv * wv.z);
    y.w = roundtf(v.w * inv * wv.w);
    ((float4*)(out + row * D_))[tid] = y;
}

// ---------------------------------------------------------------------------
// Shared MMA helpers
// ---------------------------------------------------------------------------
__device__ __forceinline__ void cp16(float* dst, const float* src) {
    unsigned d = (unsigned)__cvta_generic_to_shared(dst);
    asm volatile("cp.async.cg.shared.global [%0], [%1], 16;" :: "r"(d), "l"(src));
}

__device__ __forceinline__ void mma_tf32(float* d, const unsigned* a, const unsigned* b) {
    asm volatile("mma.sync.aligned.m16n8k8.row.col.f32.tf32.tf32.f32 "
                 "{%0,%1,%2,%3}, {%4,%5,%6,%7}, {%8,%9}, {%0,%1,%2,%3};"
                 : "+f"(d[0]), "+f"(d[1]), "+f"(d[2]), "+f"(d[3])
                 : "r"(a[0]), "r"(a[1]), "r"(a[2]), "r"(a[3]),
                   "r"(b[0]), "r"(b[1]));
}

// GELU(tanh approx) with HW MUFU.TANH (sm_75+); approx err ~1e-5 rel.
__device__ __forceinline__ float gelu_tanh(float x) {
    float u = 0.7978845608028654f * (x + 0.044715f * x * x * x);
    float th;
    asm("tanh.approx.f32 %0, %1;" : "=f"(th) : "f"(u));
    return 0.5f * x * (1.f + th);
}

// ---------------------------------------------------------------------------
// Fused causal flash attention (known good)
// ---------------------------------------------------------------------------
#define QSTR 100
#define VSTR 104
#define PSTR 68
#define KBUF (64 * QSTR)
#define VBUF (64 * VSTR)
#define OFF_K (128 * QSTR)
#define OFF_V (OFF_K + 2 * KBUF)
#define OFF_P (OFF_V + 2 * VBUF)
#define ATT_SMEM ((OFF_P + 128 * PSTR) * 4)

__global__ void __launch_bounds__(256) attn_fused_kernel(
    const float* __restrict__ q, const float* __restrict__ k,
    const float* __restrict__ v, float* __restrict__ o, float scale)
{
    int mb = blockIdx.x;
    int z = blockIdx.y;
    int b = z >> 3, h = z & 7;
    int m0 = mb * 128;
    long long qbase = ((long long)b * S_ + m0) * D_ + h * DH_;
    long long kvbase = ((long long)b * S_) * D_ + h * DH_;

    extern __shared__ float sm[];
    float* QS = sm;
    float* KS = sm + OFF_K;
    float* VS = sm + OFF_V;
    float* PS = sm + OFF_P;

    int tid = threadIdx.x;
    int warp = tid >> 5, lane = tid & 31;
    int g = lane >> 2, t = lane & 3;
    int wrow = warp * 16;

    #pragma unroll
    for (int i = 0; i < 12; i++) {
        int f = tid + i * 256;
        int r = f / 24, c = f % 24;
        cp16(QS + r * QSTR + c * 4, q + qbase + (long long)r * D_ + c * 4);
    }
    {
        #pragma unroll
        for (int i = 0; i < 6; i++) {
            int f = tid + i * 256;
            int r = f / 24, c = f % 24;
            cp16(KS + r * QSTR + c * 4, k + kvbase + (long long)r * D_ + c * 4);
        }
        #pragma unroll
        for (int i = 0; i < 6; i++) {
            int f = tid + i * 256;
            int r = f / 24, c = f % 24;
            cp16(VS + r * VSTR + c * 4, v + kvbase + (long long)r * D_ + c * 4);
        }
    }
    asm volatile("cp.async.commit_group;" ::: "memory");

    float accO[12][4];
    #pragma unroll
    for (int i = 0; i < 12; i++)
        #pragma unroll
        for (int r = 0; r < 4; r++) accO[i][r] = 0.f;
    float mrow[2] = {-1e30f, -1e30f};
    float lrow[2] = {0.f, 0.f};

    int kb_last = 2 * mb + 1;
    for (int kb = 0; kb <= kb_last; kb++) {
        asm volatile("cp.async.wait_group 0;" ::: "memory");
        __syncthreads();

        if (kb < kb_last) {
            int nb = (kb + 1) & 1;
            long long kr = kvbase + (long long)(kb + 1) * 64 * D_;
            #pragma unroll
            for (int i = 0; i < 6; i++) {
                int f = tid + i * 256;
                int r = f / 24, c = f % 24;
                cp16(KS + nb * KBUF + r * QSTR + c * 4, k + kr + (long long)r * D_ + c * 4);
            }
            #pragma unroll
            for (int i = 0; i < 6; i++) {
                int f = tid + i * 256;
                int r = f / 24, c = f % 24;
                cp16(VS + nb * VBUF + r * VSTR + c * 4, v + kr + (long long)r * D_ + c * 4);
            }
            asm volatile("cp.async.commit_group;" ::: "memory");
        }

        const unsigned* Qu = (const unsigned*)QS;
        const unsigned* Ku = (const unsigned*)(KS + (kb & 1) * KBUF);
        const unsigned* Vu = (const unsigned*)(VS + (kb & 1) * VBUF);

        float s[8][4];
        #pragma unroll
        for (int i = 0; i < 8; i++)
            #pragma unroll
            for (int r = 0; r < 4; r++) s[i][r] = 0.f;

        #pragma unroll
        for (int ks = 0; ks < 12; ks++) {
            int krow = ks * 8 + t;
            unsigned af[4];
            af[0] = Qu[(wrow + g) * QSTR + krow];
            af[1] = Qu[(wrow + g + 8) * QSTR + krow];
            af[2] = Qu[(wrow + g) * QSTR + krow + 4];
            af[3] = Qu[(wrow + g + 8) * QSTR + krow + 4];
            #pragma unroll
            for (int nt = 0; nt < 8; nt++) {
                int n = nt * 8 + g;
                unsigned bf[2];
                bf[0] = Ku[n * QSTR + krow];
                bf[1] = Ku[n * QSTR + krow + 4];
                mma_tf32(s[nt], af, bf);
            }
        }

        int j0 = kb * 64;
        #pragma unroll
        for (int nt = 0; nt < 8; nt++) {
            #pragma unroll
            for (int r = 0; r < 4; r++) {
                int row = m0 + wrow + g + ((r & 2) ? 8 : 0);
                int col = j0 + nt * 8 + 2 * t + (r & 1);
                float val = s[nt][r] * scale;
                s[nt][r] = (col > row) ? -1e30f : val;
            }
        }

        #pragma unroll
        for (int hh = 0; hh < 2; hh++) {
            float mx = -1e30f;
            #pragma unroll
            for (int nt = 0; nt < 8; nt++)
                mx = fmaxf(mx, fmaxf(s[nt][2 * hh], s[nt][2 * hh + 1]));
            mx = fmaxf(mx, __shfl_xor_sync(~0u, mx, 1));
            mx = fmaxf(mx, __shfl_xor_sync(~0u, mx, 2));
            float mnew = fmaxf(mrow[hh], mx);
            float alpha = __expf(mrow[hh] - mnew);
            mrow[hh] = mnew;
            #pragma unroll
            for (int nt = 0; nt < 12; nt++) {
                accO[nt][2 * hh]     *= alpha;
                accO[nt][2 * hh + 1] *= alpha;
            }
            float sum = 0.f;
            #pragma unroll
            for (int nt = 0; nt < 8; nt++) {
                float p0 = __expf(s[nt][2 * hh] - mnew);
                float p1 = __expf(s[nt][2 * hh + 1] - mnew);
                s[nt][2 * hh] = p0;
                s[nt][2 * hh + 1] = p1;
                sum += p0 + p1;
            }
            sum += __shfl_xor_sync(~0u, sum, 1);
            sum += __shfl_xor_sync(~0u, sum, 2);
            lrow[hh] = lrow[hh] * alpha + sum;
        }

        #pragma unroll
        for (int nt = 0; nt < 8; nt++) {
            #pragma unroll
            for (int r = 0; r < 4; r++) {
                int row = wrow + g + ((r & 2) ? 8 : 0);
                int col = nt * 8 + 2 * t + (r & 1);
                PS[row * PSTR + col] = roundtf(s[nt][r]);
            }
        }

        const unsigned* Pu = (const unsigned*)PS;
        #pragma unroll
        for (int ks = 0; ks < 8; ks++) {
            int krow = ks * 8 + t;
            unsigned af[4];
            af[0] = Pu[(wrow + g) * PSTR + krow];
            af[1] = Pu[(wrow + g + 8) * PSTR + krow];
            af[2] = Pu[(wrow + g) * PSTR + krow + 4];
            af[3] = Pu[(wrow + g + 8) * PSTR + krow + 4];
            #pragma unroll
            for (int nt = 0; nt < 12; nt++) {
                int n = nt * 8 + g;
                unsigned bf[2];
                bf[0] = Vu[krow * VSTR + n];
                bf[1] = Vu[(krow + 4) * VSTR + n];
                mma_tf32(accO[nt], af, bf);
            }
        }
    }

    float inv0 = 1.f / lrow[0];
    float inv1 = 1.f / lrow[1];
    #pragma unroll
    for (int nt = 0; nt < 12; nt++) {
        #pragma unroll
        for (int r = 0; r < 4; r++) {
            int row = wrow + g + ((r & 2) ? 8 : 0);
            int col = nt * 8 + 2 * t + (r & 1);
            float val = accO[nt][r] * ((r & 2) ? inv1 : inv0);
            o[qbase + (long long)row * D_ + col] = roundtf(val);
        }
    }
}

// ---------------------------------------------------------------------------
// TF32 tensor-core GEMM, cp.async PP-stage pipeline (single fragment buffer).
// 2 CTA/SM small-tile config — empirically optimal (R7/R12 both directions).
// ---------------------------------------------------------------------------
template <bool TRANSB, int BM, int BN, int PP>
__global__ void __launch_bounds__(256, 2) gemm_tc_async(
    const float* __restrict__ A, int lda, long long saO, long long saI,
    const float* __restrict__ Bp, int ldb, long long sbO, long long sbI,
    float* __restrict__ C, int ldc, long long scO, long long scI,
    const float* __restrict__ R,
    int M, int N, int K, float alpha, int gelu_flag, int round_flag,
    int mode, int kcap, int hdiv, MultiPtr P, int nmulti)
{
    constexpr int WM = BM / 32;
    constexpr int WN = 8 / WM;
    constexpr int WTN = BN / WN;
    constexpr int NT = WTN / 8;
    constexpr int BSTR = BN + 8;
    constexpr int BFLc = TRANSB ? BN * 36 : 32 * BSTR;
    constexpr int STAGE = BM * 36 + BFLc;
    constexpr int BCH = BN / 4;

    extern __shared__ float smf[];

    int z = blockIdx.z;
    if (nmulti > 1) {
        Bp = P.B[z];
        C = P.C[z];
    } else {
        int zo = z / hdiv, zi = z % hdiv;
        A  += (long long)zo * saO + (long long)zi * saI;
        Bp += (long long)zo * sbO + (long long)zi * sbI;
        long long co = (long long)zo * scO + (long long)zi * scI;
        C += co;
        if (R) R += co;
    }

    int m0, n0;
    if (mode == 2) {
        int p = blockIdx.x;
        int bm = 0;
        while ((bm + 1) * (bm + 2) / 2 <= p) bm++;
        int bn = p - bm * (bm + 1) / 2;
        m0 = bm * BM; n0 = bn * BN;
    } else if (mode == 1) {
        m0 = blockIdx.x * BM; n0 = blockIdx.y * BN;
    } else {
        m0 = blockIdx.y * BM; n0 = blockIdx.x * BN;
    }
    if (kcap) K = min(K, m0 + BM);

    int tid = threadIdx.x;
    int warp = tid >> 5, lane = tid & 31;
    int g = lane >> 2, t = lane & 3;
    int mwarp = (warp % WM) * 32;
    int nwarp = (warp / WM) * WTN;

    float acc[2][NT][4];
    #pragma unroll
    for (int i = 0; i < 2; i++)
        #pragma unroll
        for (int j = 0; j < NT; j++)
            #pragma unroll
            for (int r = 0; r < 4; r++) acc[i][j][r] = 0.f;

    const int KT = K >> 5;

    auto stage = [&](int kt, int sbuf) {
        float* Asf = smf + sbuf * STAGE;
        float* Bsf = Asf + BM * 36;
        int k0 = kt * 32;
        #pragma unroll
        for (int i = 0; i < BM / 32; i++) {
            int f = tid + i * 256;
            int row = f >> 3, ch = f & 7;
            cp16(Asf + row * 36 + ch * 4,
                 A + (long long)(m0 + row) * lda + k0 + ch * 4);
        }
        if (TRANSB) {
            #pragma unroll
            for (int i = 0; i < BN / 32; i++) {
                int f = tid + i * 256;
                int row = f >> 3, ch = f & 7;
                cp16(Bsf + row * 36 + ch * 4,
                     Bp + (long long)(n0 + row) * ldb + k0 + ch * 4);
            }
        } else {
            #pragma unroll
            for (int i = 0; i < (32 * BCH) / 256; i++) {
                int f = tid + i * 256;
                int kk = f / BCH, ch = f % BCH;
                cp16(Bsf + kk * BSTR + ch * 4,
                     Bp + (long long)(k0 + kk) * ldb + n0 + ch * 4);
            }
        }
        asm volatile("cp.async.commit_group;" ::: "memory");
    };

    for (int s = 0; s < PP - 1 && s < KT; s++) stage(s, s);

    for (int kt = 0; kt < KT; kt++) {
        if (kt == KT - 1) asm volatile("cp.async.wait_group 0;" ::: "memory");
        else              asm volatile("cp.async.wait_group %0;" :: "n"(PP - 2) : "memory");
        __syncthreads();

        int nk = kt + PP - 1;
        if (nk < KT) stage(nk, nk % PP);

        const unsigned* Asu = (const unsigned*)(smf + (kt % PP) * STAGE);
        const unsigned* Bsu = Asu + BM * 36;

        #pragma unroll
        for (int ks = 0; ks < 4; ks++) {
            int krow = ks * 8 + t;
            unsigned af[2][4];
            #pragma unroll
            for (int mt = 0; mt < 2; mt++) {
                int m = mwarp + mt * 16 + g;
                af[mt][0] = Asu[m * 36 + krow];
                af[mt][1] = Asu[(m + 8) * 36 + krow];
                af[mt][2] = Asu[m * 36 + krow + 4];
                af[mt][3] = Asu[(m + 8) * 36 + krow + 4];
            }
            unsigned bf[NT][2];
            #pragma unroll
            for (int nt = 0; nt < NT; nt++) {
                int n = nwarp + nt * 8 + g;
                if (TRANSB) {
                    bf[nt][0] = Bsu[n * 36 + krow];
                    bf[nt][1] = Bsu[n * 36 + krow + 4];
                } else {
                    bf[nt][0] = Bsu[krow * BSTR + n];
                    bf[nt][1] = Bsu[(krow + 4) * BSTR + n];
                }
            }
            #pragma unroll
            for (int mt = 0; mt < 2; mt++)
                #pragma unroll
                for (int nt = 0; nt < NT; nt++)
                    mma_tf32(acc[mt][nt], af[mt], bf[nt]);
        }
    }

    #pragma unroll
    for (int mt = 0; mt < 2; mt++) {
        #pragma unroll
        for (int nt = 0; nt < NT; nt++) {
            #pragma unroll
            for (int r = 0; r < 4; r++) {
                int row = m0 + mwarp + mt * 16 + g + ((r & 2) ? 8 : 0);
                int col = n0 + nwarp + nt * 8 + t * 2 + (r & 1);
                if (row < M && col < N) {
                    float v = acc[mt][nt][r] * alpha;
                    if (R) v += R[(long long)row * ldc + col];
                    if (gelu_flag) v = gelu_tanh(v);
                    if (round_flag) v = roundtf(v);
                    C[(long long)row * ldc + col] = v;
                }
            }
        }
    }
}

// ---------------------------------------------------------------------------
// Host launch helpers
// ---------------------------------------------------------------------------
template <bool TB, int BM, int BN, int PP>
static void run_gemm(dim3 grid,
                     const float* A, int lda, long long saO, long long saI,
                     const float* Bp, int ldb, long long sbO, long long sbI,
                     float* C, int ldc, long long scO, long long scI,
                     const float* R, int M, int N, int K,
                     float alpha, int gelu_flag, int round_flag,
                     int mode, int kcap, int hdiv, MultiPtr mp, int nmulti)
{
    constexpr int BFLc = TB ? BN * 36 : 32 * (BN + 8);
    size_t smem = (size_t)PP * (BM * 36 + BFLc) * sizeof(float);
    cudaFuncSetAttribute(gemm_tc_async<TB, BM, BN, PP>,
                         cudaFuncAttributeMaxDynamicSharedMemorySize, (int)smem);
    gemm_tc_async<TB, BM, BN, PP><<<grid, 256, smem>>>(A, lda, saO, saI, Bp, ldb, sbO, sbI,
                                                       C, ldc, scO, scI, R, M, N, K,
                                                       alpha, gelu_flag, round_flag,
                                                       mode, kcap, hdiv, mp, nmulti);
}

static void cvt_weights(const float* src, float* dst, long long n) {
    cvt_tf32_kernel<<<4736, 256>>>((const float4*)src, (float4*)dst, n >> 2);
}

extern "C" void kernel_launch(void* const* d_in, const int* in_sizes, int n_in,
                              void* d_out, int out_size) {
    const int*   tok         = (const int*)d_in[0];
    const float* tok_emb     = (const float*)d_in[1];
    const float* pos_emb     = (const float*)d_in[2];
    const float* pos_norm_w  = (const float*)d_in[3];
    const float* attn_norm_w = (const float*)d_in[4];
    const float* wq          = (const float*)d_in[5];
    const float* wk          = (const float*)d_in[6];
    const float* wv          = (const float*)d_in[7];
    const float* wo          = (const float*)d_in[8];
    const float* ffn_norm_w  = (const float*)d_in[9];
    const float* w1          = (const float*)d_in[10];
    const float* w2          = (const float*)d_in[11];
    const float* out_norm_w  = (const float*)d_in[12];
    const float* out_w       = (const float*)d_in[13];
    float* out = (float*)d_out;

    float *x, *xn, *q, *k, *v, *o, *ffn;
    float *cwq, *cwk, *cwv, *cwo, *cw1, *cw2, *cow;
    cudaGetSymbolAddress((void**)&x,   g_x);
    cudaGetSymbolAddress((void**)&xn,  g_xn);
    cudaGetSymbolAddress((void**)&q,   g_q);
    cudaGetSymbolAddress((void**)&k,   g_k);
    cudaGetSymbolAddress((void**)&v,   g_v);
    cudaGetSymbolAddress((void**)&o,   g_o);
    cudaGetSymbolAddress((void**)&ffn, g_ffn);
    cudaGetSymbolAddress((void**)&cwq, g_cwq);
    cudaGetSymbolAddress((void**)&cwk, g_cwk);
    cudaGetSymbolAddress((void**)&cwv, g_cwv);
    cudaGetSymbolAddress((void**)&cwo, g_cwo);
    cudaGetSymbolAddress((void**)&cw1, g_cw1);
    cudaGetSymbolAddress((void**)&cw2, g_cw2);
    cudaGetSymbolAddress((void**)&cow, g_cow);

    const float scale = 0.102062072615966f;  // 1/sqrt(96)
    MultiPtr mp0 = {};

    // Pre-round weights to tf32
    cvt_weights(wq, cwq, (long long)L_ * D_ * D_);
    cvt_weights(wk, cwk, (long long)L_ * D_ * D_);
    cvt_weights(wv, cwv, (long long)L_ * D_ * D_);
    cvt_weights(wo, cwo, (long long)L_ * D_ * D_);
    cvt_weights(w1, cw1, (long long)L_ * D_ * F_);
    cvt_weights(w2, cw2, (long long)L_ * F_ * D_);
    cvt_weights(out_w, cow, (long long)D_ * V_);

    cudaFuncSetAttribute(attn_fused_kernel,
                         cudaFuncAttributeMaxDynamicSharedMemorySize, ATT_SMEM);

    embed_norm_kernel<<<BS_, 256>>>(tok, tok_emb, pos_emb, pos_norm_w);

    for (int l = 0; l < L_; l++) {
        const float* lwq = cwq + (long long)l * D_ * D_;
        const float* lwk = cwk + (long long)l * D_ * D_;
        const float* lwv = cwv + (long long)l * D_ * D_;
        const float* lwo = cwo + (long long)l * D_ * D_;
        const float* lw1 = cw1 + (long long)l * D_ * F_;
        const float* lw2 = cw2 + (long long)l * F_ * D_;

        rmsnorm_kernel<<<BS_, 192>>>(x, xn, attn_norm_w + (long long)l * D_);

        // fused QKV (outputs rounded)
        MultiPtr mq;
        mq.B[0] = lwq; mq.B[1] = lwk; mq.B[2] = lwv;
        mq.C[0] = q;   mq.C[1] = k;   mq.C[2] = v;
        run_gemm<false, 128, 128, 3>(dim3(6, 16, 3),
                                     xn, D_, 0, 0, lwq, D_, 0, 0, q, D_, 0, 0,
                                     nullptr, BS_, D_, D_, 1.f, 0, 1, 0, 0, 1, mq, 3);

        // fused causal attention: o = softmax(scale * q k^T) v
        attn_fused_kernel<<<dim3(8, 16), 256, ATT_SMEM>>>(q, k, v, o, scale);

        // x = x + o @ wo  (BN=96: 256 CTAs, better wave packing)
        run_gemm<false, 64, 96, 4>(dim3(8, 32, 1),
                                   o, D_, 0, 0, lwo, D_, 0, 0, x, D_, 0, 0,
                                   x, BS_, D_, D_, 1.f, 0, 0, 0, 0, 1, mp0, 1);

        rmsnorm_kernel<<<BS_, 192>>>(x, xn, ffn_norm_w + (long long)l * D_);

        // ffn = round(gelu(xn @ w1))
        run_gemm<false, 128, 128, 3>(dim3(16, 16, 1),
                                     xn, D_, 0, 0, lw1, F_, 0, 0, ffn, F_, 0, 0,
                                     nullptr, BS_, F_, D_, 1.f, 1, 1, 0, 0, 1, mp0, 1);

        // x = x + ffn @ w2  (BN=96: 256 CTAs)
        run_gemm<false, 64, 96, 4>(dim3(8, 32, 1),
                                   ffn, F_, 0, 0, lw2, D_, 0, 0, x, D_, 0, 0,
                                   x, BS_, D_, F_, 1.f, 0, 0, 0, 0, 1, mp0, 1);
    }

    rmsnorm_kernel<<<BS_, 192>>>(x, xn, out_norm_w);
    // logits: swapped raster (m fastest) so concurrent CTAs share out_w tiles in L2
    run_gemm<false, 128, 128, 3>(dim3(16, 250, 1),
                                 xn, D_, 0, 0, cow, V_, 0, 0, out, V_, 0, 0,
                                 nullptr, BS_, V_, D_, 1.f, 0, 0, 1, 0, 1, mp0, 1);
}